// round 13
// baseline (speedup 1.0000x reference)
#include <cuda_runtime.h>
#include <math.h>

// NUFFTLayerMultiChannel: B=16, N=1024, M=2049, two output channels.
// Spread (sorted + windowed Gaussian) -> half-spectrum DFT with real-input
// fold -> real even k-multiplier -> inverse DFT with output fold -> windowed
// Gaussian interpolation -> /M.
// Transforms: 1024-thread blocks; 8 thread-slices per output bin each sum a
// 128-wide slice of the reduction via one in-register rotation stream;
// partials combined via smem. 8 warps/SMSP hides the FMA rotation chain.

#define MM 2049
#define BB 16
#define NN 1024
#define KH 1025   // k (or j) = 0..1024

static __device__ float  g_xg[MM];          // XGRID (fp32, via exact f64 path)
static __device__ float2 g_tw[MM];          // (cos, sin)(2*pi*r/M)
static __device__ float  g_w1[KH];          // (L/2pi)*deconv^2*m1
static __device__ float  g_w2[KH];          // (L/2pi)*deconv^2*m2
static __device__ float  g_ps[BB * NN];     // sorted p = x*(2pi/L) per batch
static __device__ float  g_gsum[BB * MM];   // gridded density
static __device__ float4 g_A[BB * KH];      // (W1*F.re, W1*F.im, W2*F.re, W2*F.im)
static __device__ float  g_ir[BB * 2 * MM]; // irfft (B, 2, M)

// ---------------------------------------------------------------------------
// K1a: per-batch bitonic sort of p = x*(2pi/L)  +  table slice (fused k0).
// Block b sorts batch b and computes table entries [b*129, b*129+129).
// ---------------------------------------------------------------------------
__global__ void k1a_sort(const float* __restrict__ x,
                         const float* __restrict__ s0, const float* __restrict__ a0,
                         const float* __restrict__ s1, const float* __restrict__ a1) {
    __shared__ float ps[NN];
    int b = blockIdx.x;
    const double PI = 3.14159265358979323846;
    // ---- table slice (independent of the sort; no sync needed) ----
    int tbase = b * 129;
    for (int t = threadIdx.x; t < 129; t += blockDim.x) {
        int i = tbase + t;
        if (i < MM) {
            double step = 10.0 / 2049.0;
            g_xg[i] = (float)((2.0 * PI * ((double)i * step)) / 10.0);
            double sv, cv;
            sincospi(2.0 * (double)i / (double)MM, &sv, &cv);
            g_tw[i] = make_float2((float)cv, (float)sv);
        }
        if (i < KH) {
            const double tau = 2.821e-5;
            double k2  = (double)i * (double)i;
            double dec = sqrt(PI / tau) * exp(k2 * tau);
            double base = (10.0 / (2.0 * PI)) * dec * dec;
            double sh0 = (double)s0[0], am0 = (double)a0[0];
            double sh1 = (double)s1[0], am1 = (double)a1[0];
            double m1 = -am0 * 4.0 * PI / (k2 + 25.0 * sh0 * sh0);
            double dn = k2 + 25.0 * sh1 * sh1;
            double m2 = am1 * 4.0 * PI / (dn * dn);
            g_w1[i] = (float)(base * m1);
            g_w2[i] = (float)(base * m2);
        }
    }
    // ---- bitonic sort (data-independent network => deterministic) ----
    const float cf = (float)(2.0 * 3.14159265358979323846 / 10.0);
    for (int n = threadIdx.x; n < NN; n += blockDim.x)
        ps[n] = __ldg(&x[b * NN + n]) * cf;
    __syncthreads();
    for (int k = 2; k <= NN; k <<= 1) {
        for (int j = k >> 1; j > 0; j >>= 1) {
            for (int i = threadIdx.x; i < NN; i += blockDim.x) {
                int ixj = i ^ j;
                if (ixj > i) {
                    float a = ps[i], c = ps[ixj];
                    bool up = ((i & k) == 0);
                    if (up ? (a > c) : (a < c)) { ps[i] = c; ps[ixj] = a; }
                }
            }
            __syncthreads();
        }
    }
    for (int n = threadIdx.x; n < NN; n += blockDim.x)
        g_ps[b * NN + n] = ps[n];
}

// ---------------------------------------------------------------------------
// K1b: windowed Gaussian spreading from the sorted point list.
// expf(-q/ft) is exactly +0.0f for q >= 0.0118 (fp32 underflow), so the
// window [xg-0.1087, xg+0.1087] covers every nonzero term of the dense sum.
// ---------------------------------------------------------------------------
__global__ void k1b_spread(void) {
    __shared__ float ps[NN];
    int b = blockIdx.y;
    for (int n = threadIdx.x; n < NN; n += blockDim.x)
        ps[n] = g_ps[b * NN + n];
    __syncthreads();
    int m = blockIdx.x * blockDim.x + threadIdx.x;
    if (m >= MM) return;
    const float xg = g_xg[m];
    const float wlo = xg - 0.1087f, whi = xg + 0.1087f;
    int l = 0, r = NN;                       // first index with ps >= wlo
    while (l < r) { int mid = (l + r) >> 1; if (ps[mid] < wlo) l = mid + 1; else r = mid; }
    const float ft = (float)(4.0 * 2.821e-5);
    float acc = 0.0f;
    for (int n = l; n < NN; ++n) {
        float p = ps[n];
        if (p > whi) break;
        float d = p - xg;
        float q = d * d;
        if (q < 0.0118f) acc += expf((-q) / ft);
    }
    g_gsum[b * MM + m] = acc;
}

// ---------------------------------------------------------------------------
// K2: half-spectrum DFT with real-input fold + combined multipliers.
// Re F[k] = g0 + sum_{m=1}^{1024} (g[m]+g[M-m]) cos(2pi k m/M)
// Im F[k] = -   sum_{m=1}^{1024} (g[m]-g[M-m]) sin(2pi k m/M)
// 1024 threads = 8 slices x 128 k-bins; slice q sums m in [1+128q, 128+128q]
// via one rotation stream of 128; partials combined in smem.
// ---------------------------------------------------------------------------
__global__ void k2_dft(void) {
    __shared__ float2 tws[MM];
    __shared__ float2 gpm[KH];
    __shared__ float2 part[8][128];
    int b = blockIdx.y;
    const float* __restrict__ gs = g_gsum + b * MM;
    for (int i = threadIdx.x; i < MM; i += blockDim.x) tws[i] = g_tw[i];
    for (int i = threadIdx.x; i < KH; i += blockDim.x) {
        if (i == 0) gpm[0] = make_float2(gs[0], 0.0f);
        else        gpm[i] = make_float2(gs[i] + gs[MM - i], gs[i] - gs[MM - i]);
    }
    __syncthreads();
    int kl    = threadIdx.x & 127;
    int slice = threadIdx.x >> 7;
    int k = blockIdx.x * 128 + kl;
    float re = 0.0f, im = 0.0f;
    if (k < KH) {
        const float2 tk = tws[k];
        int mbase = 1 + 128 * slice;
        int r0 = (int)(((long long)k * mbase) % MM);
        float2 t0 = tws[r0];
        float c = t0.x, s = t0.y;
#pragma unroll 4
        for (int it = 0; it < 128; ++it) {
            float2 gv = gpm[mbase + it];
            re = fmaf(gv.x, c, re);
            im = fmaf(gv.y, s, im);
            float cn = fmaf(c, tk.x, -(s * tk.y));
            float sn = fmaf(s, tk.x,  (c * tk.y));
            c = cn; s = sn;
        }
    }
    part[slice][kl] = make_float2(re, im);
    __syncthreads();
    if (slice == 0 && k < KH) {
        float reT = gpm[0].x +
            (((part[0][kl].x + part[1][kl].x) + (part[2][kl].x + part[3][kl].x)) +
             ((part[4][kl].x + part[5][kl].x) + (part[6][kl].x + part[7][kl].x)));
        float imT = -(((part[0][kl].y + part[1][kl].y) + (part[2][kl].y + part[3][kl].y)) +
                      ((part[4][kl].y + part[5][kl].y) + (part[6][kl].y + part[7][kl].y)));
        float w1 = g_w1[k], w2 = g_w2[k];
        g_A[b * KH + k] = make_float4(w1 * reT, w1 * imT, w2 * reT, w2 * imT);
    }
}

// ---------------------------------------------------------------------------
// K4: inverse DFT with output fold (one bin -> mesh points j and M-j).
// irfft[j]   = (A0 + 2*(U - V))/M,  irfft[M-j] = (A0 + 2*(U + V))/M
// U = sum_k ReA cos(2pi j k/M),  V = sum_k ImA sin(2pi j k/M)
// 1024 threads = 8 slices x 128 j-bins; slice q sums k in [1+128q, 128+128q]
// via one rotation stream of 128. Partials overlay tws (all tws reads are
// register-captured before the overlay sync) to stay under the 48KB limit.
// ---------------------------------------------------------------------------
__global__ void k4_idft(void) {
    __shared__ __align__(16) float2 tws[MM];
    __shared__ float4 As[KH];
    int b = blockIdx.y;
    for (int i = threadIdx.x; i < MM; i += blockDim.x) tws[i] = g_tw[i];
    for (int i = threadIdx.x; i < KH; i += blockDim.x) As[i] = g_A[b * KH + i];
    __syncthreads();
    int jl    = threadIdx.x & 127;
    int slice = threadIdx.x >> 7;
    int j = blockIdx.x * 128 + jl;
    bool act = (j < KH);
    float2 tj = make_float2(1.0f, 0.0f);
    float c = 1.0f, s = 0.0f;
    int kbase = 1 + 128 * slice;
    if (act) {
        tj = tws[j];
        int r0 = (int)(((long long)j * kbase) % MM);
        float2 t0 = tws[r0];
        c = t0.x; s = t0.y;
    }
    __syncthreads();                       // tws reads done; overlay below
    float4* part = (float4*)tws;           // 8*128 float4 = 16KB <= sizeof(tws)
    float u1 = 0.0f, v1 = 0.0f, u2 = 0.0f, v2 = 0.0f;
    if (act) {
#pragma unroll 4
        for (int it = 0; it < 128; ++it) {
            float4 a = As[kbase + it];
            u1 = fmaf(a.x, c, u1);
            v1 = fmaf(a.y, s, v1);
            u2 = fmaf(a.z, c, u2);
            v2 = fmaf(a.w, s, v2);
            float cn = fmaf(c, tj.x, -(s * tj.y));
            float sn = fmaf(s, tj.x,  (c * tj.y));
            c = cn; s = sn;
        }
    }
    part[slice * 128 + jl] = make_float4(u1, v1, u2, v2);
    __syncthreads();
    if (slice == 0 && act) {
        float U1 = 0.0f, V1 = 0.0f, U2 = 0.0f, V2 = 0.0f;
#pragma unroll
        for (int q = 0; q < 8; ++q) {
            float4 p = part[q * 128 + jl];
            U1 += p.x; V1 += p.y; U2 += p.z; V2 += p.w;
        }
        const float invM = (float)(1.0 / 2049.0);
        float4 a0 = As[0];
        float* __restrict__ ir1 = g_ir + (b * 2 + 0) * MM;
        float* __restrict__ ir2 = g_ir + (b * 2 + 1) * MM;
        ir1[j] = (a0.x + 2.0f * (U1 - V1)) * invM;
        ir2[j] = (a0.z + 2.0f * (U2 - V2)) * invM;
        if (j > 0) {
            ir1[MM - j] = (a0.x + 2.0f * (U1 + V1)) * invM;
            ir2[MM - j] = (a0.z + 2.0f * (U2 + V2)) * invM;
        }
    }
}

// ---------------------------------------------------------------------------
// K5: inverse interpolation back to the points (reference-exact fp32 g)
// ---------------------------------------------------------------------------
__global__ void k5_gather(const float* __restrict__ x, float* __restrict__ out) {
    int idx = blockIdx.x * blockDim.x + threadIdx.x;   // b*NN + n
    if (idx >= BB * NN) return;
    int b = idx >> 10;
    const float cf = (float)(2.0 * 3.14159265358979323846 / 10.0);
    float p  = __ldg(&x[idx]) * cf;
    float jf = p * (float)(2049.0 / (2.0 * 3.14159265358979323846));
    int lo = (int)jf - 37; if (lo < 0) lo = 0;
    int hi = (int)jf + 37; if (hi > MM - 1) hi = MM - 1;
    const float ft = (float)(4.0 * 2.821e-5);
    const float* __restrict__ ir1 = g_ir + (b * 2 + 0) * MM;
    const float* __restrict__ ir2 = g_ir + (b * 2 + 1) * MM;
    float a1 = 0.0f, a2 = 0.0f;
    for (int j = lo; j <= hi; ++j) {
        float d = p - g_xg[j];
        float q = d * d;
        if (q < 0.0118f) {
            float g = expf((-q) / ft);
            a1 = fmaf(__ldg(&ir1[j]), g, a1);
            a2 = fmaf(__ldg(&ir2[j]), g, a2);
        }
    }
    out[idx * 2 + 0] = a1 / 2049.0f;
    out[idx * 2 + 1] = a2 / 2049.0f;
}

// ---------------------------------------------------------------------------
extern "C" void kernel_launch(void* const* d_in, const int* in_sizes, int n_in,
                              void* d_out, int out_size) {
    const float* x  = (const float*)d_in[0];
    const float* s0 = (const float*)d_in[1];
    const float* a0 = (const float*)d_in[2];
    const float* s1 = (const float*)d_in[3];
    const float* a1 = (const float*)d_in[4];
    float* out = (float*)d_out;

    k1a_sort <<<BB, 512>>>(x, s0, a0, s1, a1);
    k1b_spread<<<dim3((MM + 255) / 256, BB), 256>>>();
    k2_dft   <<<dim3((KH + 127) / 128, BB), 1024>>>();
    k4_idft  <<<dim3((KH + 127) / 128, BB), 1024>>>();
    k5_gather<<<(BB * NN + 255) / 256, 256>>>(x, out);
}

// round 15
// speedup vs baseline: 1.1819x; 1.1819x over previous
#include <cuda_runtime.h>
#include <math.h>

// NUFFTLayerMultiChannel: B=16, N=1024, M=2049, two output channels.
// k1: fused table-gen + windowed spreading with order-preserving candidate
//     compaction (bit-exact vs reference dense sum: dropped terms are +0.0f).
// k2/k4: DFT / inverse DFT with symmetry folds; packed f32x2 FMA (FFMA2),
//     two bins per thread, 8 reduction slices, in-register rotation streams.
// k5: windowed Gaussian interpolation back to points.

#define MM 2049
#define BB 16
#define NN 1024
#define KH 1025   // k (or j) = 0..1024

static __device__ float  g_xg[MM];          // XGRID (fp32, via exact f64 path)
static __device__ float2 g_tw[MM];          // (cos, sin)(2*pi*r/M)
static __device__ float  g_w1[KH];          // (L/2pi)*deconv^2*m1
static __device__ float  g_w2[KH];          // (L/2pi)*deconv^2*m2
static __device__ float  g_gsum[BB * MM];   // gridded density
static __device__ float4 g_A[BB * KH];      // (W1*F.re, W1*F.im, W2*F.re, W2*F.im)
static __device__ float  g_ir[BB * 2 * MM]; // irfft (B, 2, M)

// ---- packed f32x2 helpers (sm_10x) ----------------------------------------
typedef unsigned long long u64b;
__device__ __forceinline__ u64b pk2(float lo, float hi) {
    u64b r; asm("mov.b64 %0,{%1,%2};" : "=l"(r) : "f"(lo), "f"(hi)); return r;
}
__device__ __forceinline__ void upk2(u64b v, float& lo, float& hi) {
    asm("mov.b64 {%0,%1},%2;" : "=f"(lo), "=f"(hi) : "l"(v));
}
__device__ __forceinline__ u64b fma2(u64b a, u64b b, u64b c) {
    u64b d; asm("fma.rn.f32x2 %0,%1,%2,%3;" : "=l"(d) : "l"(a), "l"(b), "l"(c)); return d;
}
__device__ __forceinline__ u64b mul2(u64b a, u64b b) {
    u64b d; asm("mul.rn.f32x2 %0,%1,%2;" : "=l"(d) : "l"(a), "l"(b)); return d;
}

// ---------------------------------------------------------------------------
// K1: fused tables + windowed spreading. Grid (9, BB), 256 threads.
// Block covers cells [256*bx, 256*bx+255]. Candidates = points within
// [xg_lo-0.1095, xg_hi+0.1095]; outside-window terms are exactly +0.0f in
// fp32, and compaction preserves original n order => bit-exact dense sum.
// ---------------------------------------------------------------------------
__global__ void k1_spread(const float* __restrict__ x,
                          const float* __restrict__ s0, const float* __restrict__ a0,
                          const float* __restrict__ s1, const float* __restrict__ a1) {
    __shared__ float ps[NN];
    __shared__ float cand[NN];
    __shared__ int   cnt[256];
    const double PI = 3.14159265358979323846;
    int b = blockIdx.y;
    int tid = threadIdx.x;
    // ---- table slice: flat block id covers 15 entries ----
    int fl = blockIdx.y * gridDim.x + blockIdx.x;     // 0..143
    int i = fl * 15 + tid;
    if (tid < 15 && i < MM) {
        double step = 10.0 / 2049.0;
        g_xg[i] = (float)((2.0 * PI * ((double)i * step)) / 10.0);
        double sv, cv;
        sincospi(2.0 * (double)i / (double)MM, &sv, &cv);
        g_tw[i] = make_float2((float)cv, (float)sv);
        if (i < KH) {
            const double tau = 2.821e-5;
            double k2 = (double)i * (double)i;
            double dec = sqrt(PI / tau) * exp(k2 * tau);
            double base = (10.0 / (2.0 * PI)) * dec * dec;
            double sh0 = (double)s0[0], am0 = (double)a0[0];
            double sh1 = (double)s1[0], am1 = (double)a1[0];
            g_w1[i] = (float)(base * (-am0 * 4.0 * PI / (k2 + 25.0 * sh0 * sh0)));
            double dn = k2 + 25.0 * sh1 * sh1;
            g_w2[i] = (float)(base * (am1 * 4.0 * PI / (dn * dn)));
        }
    }
    // ---- load p values (original n order) ----
    const float cf = (float)(2.0 * 3.14159265358979323846 / 10.0);
    for (int n = tid; n < NN; n += 256)
        ps[n] = __ldg(&x[b * NN + n]) * cf;
    __syncthreads();
    // ---- window bounds for this block ----
    int m0 = blockIdx.x * 256;
    int mHi = min(m0 + 255, MM - 1);
    float wlo = (float)(2.0 * PI * (double)m0  / 2049.0) - 0.1095f;
    float whi = (float)(2.0 * PI * (double)mHi / 2049.0) + 0.1095f;
    // ---- order-preserving compaction: thread t owns n in [4t, 4t+4) ----
    float pv[4]; int c0 = 0;
#pragma unroll
    for (int q = 0; q < 4; ++q) {
        pv[q] = ps[4 * tid + q];
        if (pv[q] >= wlo && pv[q] <= whi) c0++;
    }
    cnt[tid] = c0;
    __syncthreads();
    for (int off = 1; off < 256; off <<= 1) {
        int v = cnt[tid];
        int u = (tid >= off) ? cnt[tid - off] : 0;
        __syncthreads();
        cnt[tid] = v + u;
        __syncthreads();
    }
    int total = cnt[255];
    int w = cnt[tid] - c0;   // exclusive prefix
#pragma unroll
    for (int q = 0; q < 4; ++q)
        if (pv[q] >= wlo && pv[q] <= whi) cand[w++] = pv[q];
    __syncthreads();
    // ---- spread: one cell per thread over candidates ----
    int m = m0 + tid;
    if (m < MM) {
        double step = 10.0 / 2049.0;
        float xg = (float)((2.0 * PI * ((double)m * step)) / 10.0);
        const float ft = (float)(4.0 * 2.821e-5);
        float acc = 0.0f;
        for (int c = 0; c < total; ++c) {
            float d = cand[c] - xg;
            float q = d * d;
            if (q < 0.0118f) acc += expf((-q) / ft);
        }
        g_gsum[b * MM + m] = acc;
    }
}

// ---------------------------------------------------------------------------
// K2: half-spectrum DFT with real-input fold + combined multipliers.
// 512 threads = 8 slices x 64 bin-pairs; thread handles bins (ka, ka+64),
// slice q sums m in [1+128q, 128+128q] via one packed-f32x2 rotation stream.
// ---------------------------------------------------------------------------
__global__ void k2_dft(void) {
    __shared__ float2 tws[MM];
    __shared__ float2 gpm[KH];
    __shared__ float2 part[8][128];
    int b = blockIdx.y;
    const float* __restrict__ gs = g_gsum + b * MM;
    for (int i = threadIdx.x; i < MM; i += blockDim.x) tws[i] = g_tw[i];
    for (int i = threadIdx.x; i < KH; i += blockDim.x) {
        if (i == 0) gpm[0] = make_float2(gs[0], 0.0f);
        else        gpm[i] = make_float2(gs[i] + gs[MM - i], gs[i] - gs[MM - i]);
    }
    __syncthreads();
    int t6    = threadIdx.x & 63;
    int slice = threadIdx.x >> 6;
    int ka = blockIdx.x * 128 + t6;
    int kb = ka + 64;                      // max 1151 < MM: tws reads safe
    int mbase = 1 + 128 * slice;
    float2 ta = tws[ka], tb = tws[kb];
    u64b TX  = pk2(ta.x, tb.x);
    u64b TY  = pk2(ta.y, tb.y);
    u64b NTY = pk2(-ta.y, -tb.y);
    int ra = (ka * mbase) % MM, rb = (kb * mbase) % MM;
    float2 t0a = tws[ra], t0b = tws[rb];
    u64b C = pk2(t0a.x, t0b.x);
    u64b S = pk2(t0a.y, t0b.y);
    u64b RE = pk2(0.0f, 0.0f), IM = RE;
#pragma unroll 4
    for (int it = 0; it < 128; ++it) {
        float2 gv = gpm[mbase + it];
        u64b GX = pk2(gv.x, gv.x);
        u64b GY = pk2(gv.y, gv.y);
        RE = fma2(GX, C, RE);
        IM = fma2(GY, S, IM);
        u64b Cn = fma2(S, NTY, mul2(C, TX));
        u64b Sn = fma2(S, TX,  mul2(C, TY));
        C = Cn; S = Sn;
    }
    float rea, reb, ima, imb;
    upk2(RE, rea, reb); upk2(IM, ima, imb);
    part[slice][t6]      = make_float2(rea, ima);
    part[slice][t6 + 64] = make_float2(reb, imb);
    __syncthreads();
    if (threadIdx.x < 128) {
        int k = blockIdx.x * 128 + threadIdx.x;
        if (k < KH) {
            float re = gpm[0].x, im = 0.0f;
#pragma unroll
            for (int q = 0; q < 8; ++q) {
                re += part[q][threadIdx.x].x;
                im += part[q][threadIdx.x].y;
            }
            im = -im;
            float w1 = g_w1[k], w2 = g_w2[k];
            g_A[b * KH + k] = make_float4(w1 * re, w1 * im, w2 * re, w2 * im);
        }
    }
}

// ---------------------------------------------------------------------------
// K4: inverse DFT with output fold. 512 threads = 8 slices x 64 bin-pairs;
// thread handles bins (ja, ja+64); slice q sums k in [1+128q, 128+128q].
// Partial array overlays tws (all tws reads register-captured pre-overlay).
// ---------------------------------------------------------------------------
__global__ void k4_idft(void) {
    __shared__ __align__(16) float2 tws[MM];
    __shared__ float4 As[KH];
    int b = blockIdx.y;
    for (int i = threadIdx.x; i < MM; i += blockDim.x) tws[i] = g_tw[i];
    for (int i = threadIdx.x; i < KH; i += blockDim.x) As[i] = g_A[b * KH + i];
    __syncthreads();
    int t6    = threadIdx.x & 63;
    int slice = threadIdx.x >> 6;
    int ja = blockIdx.x * 128 + t6;
    int jb = ja + 64;                      // < MM: tws reads safe
    int kbase = 1 + 128 * slice;
    float2 ta = tws[ja], tb = tws[jb];
    u64b TX  = pk2(ta.x, tb.x);
    u64b TY  = pk2(ta.y, tb.y);
    u64b NTY = pk2(-ta.y, -tb.y);
    int ra = (ja * kbase) % MM, rb = (jb * kbase) % MM;
    float2 t0a = tws[ra], t0b = tws[rb];
    u64b C = pk2(t0a.x, t0b.x);
    u64b S = pk2(t0a.y, t0b.y);
    __syncthreads();                        // tws reads done; overlay below
    float4* part = (float4*)tws;            // 8*128 float4 = 16384B <= 16392B
    u64b U1 = pk2(0.0f, 0.0f), V1 = U1, U2 = U1, V2 = U1;
#pragma unroll 4
    for (int it = 0; it < 128; ++it) {
        float4 a = As[kbase + it];
        u64b AX = pk2(a.x, a.x), AY = pk2(a.y, a.y);
        u64b AZ = pk2(a.z, a.z), AW = pk2(a.w, a.w);
        U1 = fma2(AX, C, U1);
        V1 = fma2(AY, S, V1);
        U2 = fma2(AZ, C, U2);
        V2 = fma2(AW, S, V2);
        u64b Cn = fma2(S, NTY, mul2(C, TX));
        u64b Sn = fma2(S, TX,  mul2(C, TY));
        C = Cn; S = Sn;
    }
    float u1a, u1b, v1a, v1b, u2a, u2b, v2a, v2b;
    upk2(U1, u1a, u1b); upk2(V1, v1a, v1b);
    upk2(U2, u2a, u2b); upk2(V2, v2a, v2b);
    part[slice * 128 + t6]      = make_float4(u1a, v1a, u2a, v2a);
    part[slice * 128 + t6 + 64] = make_float4(u1b, v1b, u2b, v2b);
    __syncthreads();
    if (threadIdx.x < 128) {
        int j = blockIdx.x * 128 + threadIdx.x;
        if (j < KH) {
            float U1t = 0.0f, V1t = 0.0f, U2t = 0.0f, V2t = 0.0f;
#pragma unroll
            for (int q = 0; q < 8; ++q) {
                float4 p = part[q * 128 + threadIdx.x];
                U1t += p.x; V1t += p.y; U2t += p.z; V2t += p.w;
            }
            const float invM = (float)(1.0 / 2049.0);
            float4 a0 = As[0];
            float* __restrict__ ir1 = g_ir + (b * 2 + 0) * MM;
            float* __restrict__ ir2 = g_ir + (b * 2 + 1) * MM;
            ir1[j] = (a0.x + 2.0f * (U1t - V1t)) * invM;
            ir2[j] = (a0.z + 2.0f * (U2t - V2t)) * invM;
            if (j > 0) {
                ir1[MM - j] = (a0.x + 2.0f * (U1t + V1t)) * invM;
                ir2[MM - j] = (a0.z + 2.0f * (U2t + V2t)) * invM;
            }
        }
    }
}

// ---------------------------------------------------------------------------
// K5: inverse interpolation back to the points (reference-exact fp32 g)
// ---------------------------------------------------------------------------
__global__ void k5_gather(const float* __restrict__ x, float* __restrict__ out) {
    int idx = blockIdx.x * blockDim.x + threadIdx.x;   // b*NN + n
    if (idx >= BB * NN) return;
    int b = idx >> 10;
    const float cf = (float)(2.0 * 3.14159265358979323846 / 10.0);
    float p  = __ldg(&x[idx]) * cf;
    float jf = p * (float)(2049.0 / (2.0 * 3.14159265358979323846));
    int lo = (int)jf - 37; if (lo < 0) lo = 0;
    int hi = (int)jf + 37; if (hi > MM - 1) hi = MM - 1;
    const float ft = (float)(4.0 * 2.821e-5);
    const float* __restrict__ ir1 = g_ir + (b * 2 + 0) * MM;
    const float* __restrict__ ir2 = g_ir + (b * 2 + 1) * MM;
    float a1 = 0.0f, a2 = 0.0f;
    for (int j = lo; j <= hi; ++j) {
        float d = p - g_xg[j];
        float q = d * d;
        if (q < 0.0118f) {
            float g = expf((-q) / ft);
            a1 = fmaf(__ldg(&ir1[j]), g, a1);
            a2 = fmaf(__ldg(&ir2[j]), g, a2);
        }
    }
    out[idx * 2 + 0] = a1 / 2049.0f;
    out[idx * 2 + 1] = a2 / 2049.0f;
}

// ---------------------------------------------------------------------------
extern "C" void kernel_launch(void* const* d_in, const int* in_sizes, int n_in,
                              void* d_out, int out_size) {
    const float* x  = (const float*)d_in[0];
    const float* s0 = (const float*)d_in[1];
    const float* a0 = (const float*)d_in[2];
    const float* s1 = (const float*)d_in[3];
    const float* a1 = (const float*)d_in[4];
    float* out = (float*)d_out;

    k1_spread<<<dim3(9, BB), 256>>>(x, s0, a0, s1, a1);
    k2_dft   <<<dim3(9, BB), 512>>>();
    k4_idft  <<<dim3(9, BB), 512>>>();
    k5_gather<<<(BB * NN + 255) / 256, 256>>>(x, out);
}

// round 17
// speedup vs baseline: 1.5937x; 1.3484x over previous
#include <cuda_runtime.h>
#include <math.h>

// NUFFTLayerMultiChannel: B=16, N=1024, M=2049, two output channels.
// k1: fused tables + spreading. Candidate compaction, then per-candidate
//     73-entry Gaussian rows via geometric-ratio recurrence (2 expf/candidate
//     instead of expf per (cell,point) pair); cells sum rows from smem.
// k2/k4: DFT / inverse DFT with symmetry folds; packed f32x2 FMA.
// k5: smem-staged irfft + same Gaussian recurrence per point (2 expf/point).

#define MM 2049
#define BB 16
#define NN 1024
#define KH 1025   // k (or j) = 0..1024

#define PI_D 3.14159265358979323846
#define H_D  (6.283185307179586476925287 / 2049.0)   // mesh step in rad
#define FT_D (4.0 * 2.821e-5)                        // 4*tau

static __device__ float2 g_tw[MM];          // (cos, sin)(2*pi*r/M)
static __device__ float  g_w1[KH];          // (L/2pi)*deconv^2*m1
static __device__ float  g_w2[KH];          // (L/2pi)*deconv^2*m2
static __device__ float  g_gsum[BB * MM];   // gridded density
static __device__ float4 g_A[BB * KH];      // (W1*F.re, W1*F.im, W2*F.re, W2*F.im)
static __device__ float  g_ir[BB * 2 * MM]; // irfft (B, 2, M)

// ---- packed f32x2 helpers (sm_10x) ----------------------------------------
typedef unsigned long long u64b;
__device__ __forceinline__ u64b pk2(float lo, float hi) {
    u64b r; asm("mov.b64 %0,{%1,%2};" : "=l"(r) : "f"(lo), "f"(hi)); return r;
}
__device__ __forceinline__ void upk2(u64b v, float& lo, float& hi) {
    asm("mov.b64 {%0,%1},%2;" : "=f"(lo), "=f"(hi) : "l"(v));
}
__device__ __forceinline__ u64b fma2(u64b a, u64b b, u64b c) {
    u64b d; asm("fma.rn.f32x2 %0,%1,%2,%3;" : "=l"(d) : "l"(a), "l"(b), "l"(c)); return d;
}
__device__ __forceinline__ u64b mul2(u64b a, u64b b) {
    u64b d; asm("mul.rn.f32x2 %0,%1,%2;" : "=l"(d) : "l"(a), "l"(b)); return d;
}

// ---------------------------------------------------------------------------
// K1: fused tables + spreading. Grid (9, BB), 256 threads.
// Block covers cells [256*bx, 256*bx+255]. Candidate points within
// [xg_lo-0.1095, xg_hi+0.1095]; others contribute exactly +0.0f.
// Per chunk of 64 candidates: Phase A builds 73-entry G rows (recurrence,
// 2 expf each); Phase B: cell m adds row entry at t = m - mc if |t| <= 36
// (36*h = 0.1104 > 0.10866 = fp32 support radius). n-order preserved.
// ---------------------------------------------------------------------------
__global__ void k1_spread(const float* __restrict__ x,
                          const float* __restrict__ s0, const float* __restrict__ a0,
                          const float* __restrict__ s1, const float* __restrict__ a1) {
    __shared__ float ps[NN];
    __shared__ float cand[NN];
    __shared__ int   cnt[256];
    __shared__ int   mcs[64];
    __shared__ float Grow[64 * 73];
    int b = blockIdx.y;
    int tid = threadIdx.x;
    // ---- table slice: flat block id covers 15 entries ----
    int fl = blockIdx.y * gridDim.x + blockIdx.x;     // 0..143
    int i = fl * 15 + tid;
    if (tid < 15 && i < MM) {
        double sv, cv;
        sincospi(2.0 * (double)i / (double)MM, &sv, &cv);
        g_tw[i] = make_float2((float)cv, (float)sv);
        if (i < KH) {
            const double tau = 2.821e-5;
            double k2 = (double)i * (double)i;
            double dec = sqrt(PI_D / tau) * exp(k2 * tau);
            double base = (10.0 / (2.0 * PI_D)) * dec * dec;
            double sh0 = (double)s0[0], am0 = (double)a0[0];
            double sh1 = (double)s1[0], am1 = (double)a1[0];
            g_w1[i] = (float)(base * (-am0 * 4.0 * PI_D / (k2 + 25.0 * sh0 * sh0)));
            double dn = k2 + 25.0 * sh1 * sh1;
            g_w2[i] = (float)(base * (am1 * 4.0 * PI_D / (dn * dn)));
        }
    }
    // ---- load p values (original n order) ----
    const float cf = (float)(2.0 * PI_D / 10.0);
    for (int n = tid; n < NN; n += 256)
        ps[n] = __ldg(&x[b * NN + n]) * cf;
    __syncthreads();
    // ---- window bounds for this block ----
    int m0 = blockIdx.x * 256;
    int mHi = min(m0 + 255, MM - 1);
    float wlo = (float)(2.0 * PI_D * (double)m0  / 2049.0) - 0.1095f;
    float whi = (float)(2.0 * PI_D * (double)mHi / 2049.0) + 0.1095f;
    // ---- order-preserving compaction: thread t owns n in [4t, 4t+4) ----
    float pv[4]; int c0 = 0;
#pragma unroll
    for (int q = 0; q < 4; ++q) {
        pv[q] = ps[4 * tid + q];
        if (pv[q] >= wlo && pv[q] <= whi) c0++;
    }
    cnt[tid] = c0;
    __syncthreads();
    for (int off = 1; off < 256; off <<= 1) {
        int v = cnt[tid];
        int u = (tid >= off) ? cnt[tid - off] : 0;
        __syncthreads();
        cnt[tid] = v + u;
        __syncthreads();
    }
    int total = cnt[255];
    int w = cnt[tid] - c0;   // exclusive prefix
#pragma unroll
    for (int q = 0; q < 4; ++q)
        if (pv[q] >= wlo && pv[q] <= whi) cand[w++] = pv[q];
    // ---- Gaussian recurrence constants ----
    const float ftf  = (float)FT_D;
    const float c2f  = (float)(2.0 * H_D / FT_D);
    const float c1f  = (float)(H_D * H_D / FT_D);
    const float Qf   = (float)exp(-2.0 * H_D * H_D / FT_D);
    const float invh = (float)(1.0 / H_D);
    int m = m0 + tid;
    bool mvalid = (m < MM);
    float acc = 0.0f;
    for (int cb = 0; cb < total; cb += 64) {
        int csz = min(64, total - cb);
        __syncthreads();                      // cand ready / Grow reusable
        if (tid < csz) {
            float p = cand[cb + tid];
            int mc = __float2int_rn(p * invh);
            float xgc = (float)((2.0 * PI_D * ((double)mc * (10.0 / 2049.0))) / 10.0);
            float d0 = p - xgc;
            float Gc = expf((-(d0 * d0)) / ftf);
            float U  = expf(fmaf(d0, c2f, -c1f));   // exp((2 d0 h - h^2)/ft)
            float Dn = Qf / U;                      // exp(-(2 d0 h + h^2)/ft)
            mcs[tid] = mc;
            int base = tid * 73;
            Grow[base + 36] = Gc;
            float G = Gc, R = U;
#pragma unroll
            for (int t = 1; t <= 36; ++t) { G *= R; R *= Qf; Grow[base + 36 + t] = G; }
            G = Gc; R = Dn;
#pragma unroll
            for (int t = 1; t <= 36; ++t) { G *= R; R *= Qf; Grow[base + 36 - t] = G; }
        }
        __syncthreads();
        if (mvalid) {
            for (int ci = 0; ci < csz; ++ci) {
                int t = m - mcs[ci];
                if (t >= -36 && t <= 36) acc += Grow[ci * 73 + 36 + t];
            }
        }
    }
    if (mvalid) g_gsum[b * MM + m] = acc;
}

// ---------------------------------------------------------------------------
// K2: half-spectrum DFT with real-input fold + combined multipliers.
// 512 threads = 8 slices x 64 bin-pairs; thread handles bins (ka, ka+64),
// slice q sums m in [1+128q, 128+128q] via one packed-f32x2 rotation stream.
// ---------------------------------------------------------------------------
__global__ void k2_dft(void) {
    __shared__ float2 tws[MM];
    __shared__ float2 gpm[KH];
    __shared__ float2 part[8][128];
    int b = blockIdx.y;
    const float* __restrict__ gs = g_gsum + b * MM;
    for (int i = threadIdx.x; i < MM; i += blockDim.x) tws[i] = g_tw[i];
    for (int i = threadIdx.x; i < KH; i += blockDim.x) {
        if (i == 0) gpm[0] = make_float2(gs[0], 0.0f);
        else        gpm[i] = make_float2(gs[i] + gs[MM - i], gs[i] - gs[MM - i]);
    }
    __syncthreads();
    int t6    = threadIdx.x & 63;
    int slice = threadIdx.x >> 6;
    int ka = blockIdx.x * 128 + t6;
    int kb = ka + 64;                      // max 1151 < MM: tws reads safe
    int mbase = 1 + 128 * slice;
    float2 ta = tws[ka], tb = tws[kb];
    u64b TX  = pk2(ta.x, tb.x);
    u64b TY  = pk2(ta.y, tb.y);
    u64b NTY = pk2(-ta.y, -tb.y);
    int ra = (ka * mbase) % MM, rb = (kb * mbase) % MM;
    float2 t0a = tws[ra], t0b = tws[rb];
    u64b C = pk2(t0a.x, t0b.x);
    u64b S = pk2(t0a.y, t0b.y);
    u64b RE = pk2(0.0f, 0.0f), IM = RE;
#pragma unroll 4
    for (int it = 0; it < 128; ++it) {
        float2 gv = gpm[mbase + it];
        u64b GX = pk2(gv.x, gv.x);
        u64b GY = pk2(gv.y, gv.y);
        RE = fma2(GX, C, RE);
        IM = fma2(GY, S, IM);
        u64b Cn = fma2(S, NTY, mul2(C, TX));
        u64b Sn = fma2(S, TX,  mul2(C, TY));
        C = Cn; S = Sn;
    }
    float rea, reb, ima, imb;
    upk2(RE, rea, reb); upk2(IM, ima, imb);
    part[slice][t6]      = make_float2(rea, ima);
    part[slice][t6 + 64] = make_float2(reb, imb);
    __syncthreads();
    if (threadIdx.x < 128) {
        int k = blockIdx.x * 128 + threadIdx.x;
        if (k < KH) {
            float re = gpm[0].x, im = 0.0f;
#pragma unroll
            for (int q = 0; q < 8; ++q) {
                re += part[q][threadIdx.x].x;
                im += part[q][threadIdx.x].y;
            }
            im = -im;
            float w1 = g_w1[k], w2 = g_w2[k];
            g_A[b * KH + k] = make_float4(w1 * re, w1 * im, w2 * re, w2 * im);
        }
    }
}

// ---------------------------------------------------------------------------
// K4: inverse DFT with output fold. 512 threads = 8 slices x 64 bin-pairs;
// thread handles bins (ja, ja+64); slice q sums k in [1+128q, 128+128q].
// Partial array overlays tws (all tws reads register-captured pre-overlay).
// ---------------------------------------------------------------------------
__global__ void k4_idft(void) {
    __shared__ __align__(16) float2 tws[MM];
    __shared__ float4 As[KH];
    int b = blockIdx.y;
    for (int i = threadIdx.x; i < MM; i += blockDim.x) tws[i] = g_tw[i];
    for (int i = threadIdx.x; i < KH; i += blockDim.x) As[i] = g_A[b * KH + i];
    __syncthreads();
    int t6    = threadIdx.x & 63;
    int slice = threadIdx.x >> 6;
    int ja = blockIdx.x * 128 + t6;
    int jb = ja + 64;                      // < MM: tws reads safe
    int kbase = 1 + 128 * slice;
    float2 ta = tws[ja], tb = tws[jb];
    u64b TX  = pk2(ta.x, tb.x);
    u64b TY  = pk2(ta.y, tb.y);
    u64b NTY = pk2(-ta.y, -tb.y);
    int ra = (ja * kbase) % MM, rb = (jb * kbase) % MM;
    float2 t0a = tws[ra], t0b = tws[rb];
    u64b C = pk2(t0a.x, t0b.x);
    u64b S = pk2(t0a.y, t0b.y);
    __syncthreads();                        // tws reads done; overlay below
    float4* part = (float4*)tws;            // 8*128 float4 = 16384B <= 16392B
    u64b U1 = pk2(0.0f, 0.0f), V1 = U1, U2 = U1, V2 = U1;
#pragma unroll 4
    for (int it = 0; it < 128; ++it) {
        float4 a = As[kbase + it];
        u64b AX = pk2(a.x, a.x), AY = pk2(a.y, a.y);
        u64b AZ = pk2(a.z, a.z), AW = pk2(a.w, a.w);
        U1 = fma2(AX, C, U1);
        V1 = fma2(AY, S, V1);
        U2 = fma2(AZ, C, U2);
        V2 = fma2(AW, S, V2);
        u64b Cn = fma2(S, NTY, mul2(C, TX));
        u64b Sn = fma2(S, TX,  mul2(C, TY));
        C = Cn; S = Sn;
    }
    float u1a, u1b, v1a, v1b, u2a, u2b, v2a, v2b;
    upk2(U1, u1a, u1b); upk2(V1, v1a, v1b);
    upk2(U2, u2a, u2b); upk2(V2, v2a, v2b);
    part[slice * 128 + t6]      = make_float4(u1a, v1a, u2a, v2a);
    part[slice * 128 + t6 + 64] = make_float4(u1b, v1b, u2b, v2b);
    __syncthreads();
    if (threadIdx.x < 128) {
        int j = blockIdx.x * 128 + threadIdx.x;
        if (j < KH) {
            float U1t = 0.0f, V1t = 0.0f, U2t = 0.0f, V2t = 0.0f;
#pragma unroll
            for (int q = 0; q < 8; ++q) {
                float4 p = part[q * 128 + threadIdx.x];
                U1t += p.x; V1t += p.y; U2t += p.z; V2t += p.w;
            }
            const float invM = (float)(1.0 / 2049.0);
            float4 a0 = As[0];
            float* __restrict__ ir1 = g_ir + (b * 2 + 0) * MM;
            float* __restrict__ ir2 = g_ir + (b * 2 + 1) * MM;
            ir1[j] = (a0.x + 2.0f * (U1t - V1t)) * invM;
            ir2[j] = (a0.z + 2.0f * (U2t - V2t)) * invM;
            if (j > 0) {
                ir1[MM - j] = (a0.x + 2.0f * (U1t + V1t)) * invM;
                ir2[MM - j] = (a0.z + 2.0f * (U2t + V2t)) * invM;
            }
        }
    }
}

// ---------------------------------------------------------------------------
// K5: interpolation back to points. Grid (8, BB), 128 threads, one point per
// thread. irfft staged in smem; Gaussian via center-outward recurrence
// (2 expf + 1 div per point; 2 muls + 2 FMA per cell).
// ---------------------------------------------------------------------------
__global__ void k5_gather(const float* __restrict__ x, float* __restrict__ out) {
    __shared__ float ir1s[MM];
    __shared__ float ir2s[MM];
    int b = blockIdx.y;
    for (int i = threadIdx.x; i < MM; i += 128) {
        ir1s[i] = g_ir[(b * 2 + 0) * MM + i];
        ir2s[i] = g_ir[(b * 2 + 1) * MM + i];
    }
    __syncthreads();
    int n = blockIdx.x * 128 + threadIdx.x;        // 0..1023
    const float cf   = (float)(2.0 * PI_D / 10.0);
    const float ftf  = (float)FT_D;
    const float c2f  = (float)(2.0 * H_D / FT_D);
    const float c1f  = (float)(H_D * H_D / FT_D);
    const float Qf   = (float)exp(-2.0 * H_D * H_D / FT_D);
    const float invh = (float)(1.0 / H_D);
    float p = __ldg(&x[b * NN + n]) * cf;
    int jc = __float2int_rn(p * invh);
    if (jc > 2048) jc = 2048;
    if (jc < 0) jc = 0;
    float xgc = (float)((2.0 * PI_D * ((double)jc * (10.0 / 2049.0))) / 10.0);
    float d0 = p - xgc;
    float Gc = expf((-(d0 * d0)) / ftf);
    float U  = expf(fmaf(d0, c2f, -c1f));
    float Dn = Qf / U;
    float a1 = Gc * ir1s[jc];
    float a2 = Gc * ir2s[jc];
    float G = Gc, R = U;
#pragma unroll
    for (int t = 1; t <= 36; ++t) {
        G *= R; R *= Qf;
        int j = jc + t;
        if (j <= 2048) { a1 = fmaf(G, ir1s[j], a1); a2 = fmaf(G, ir2s[j], a2); }
    }
    G = Gc; R = Dn;
#pragma unroll
    for (int t = 1; t <= 36; ++t) {
        G *= R; R *= Qf;
        int j = jc - t;
        if (j >= 0) { a1 = fmaf(G, ir1s[j], a1); a2 = fmaf(G, ir2s[j], a2); }
    }
    int idx = b * NN + n;
    out[idx * 2 + 0] = a1 / 2049.0f;
    out[idx * 2 + 1] = a2 / 2049.0f;
}

// ---------------------------------------------------------------------------
extern "C" void kernel_launch(void* const* d_in, const int* in_sizes, int n_in,
                              void* d_out, int out_size) {
    const float* x  = (const float*)d_in[0];
    const float* s0 = (const float*)d_in[1];
    const float* a0 = (const float*)d_in[2];
    const float* s1 = (const float*)d_in[3];
    const float* a1 = (const float*)d_in[4];
    float* out = (float*)d_out;

    k1_spread<<<dim3(9, BB), 256>>>(x, s0, a0, s1, a1);
    k2_dft   <<<dim3(9, BB), 512>>>();
    k4_idft  <<<dim3(9, BB), 512>>>();
    k5_gather<<<dim3(8, BB), 128>>>(x, out);
}